// round 9
// baseline (speedup 1.0000x reference)
#include <cuda_runtime.h>
#include <cstdint>

// Fixed shapes per reference
static constexpr int Bn    = 512;      // batch
static constexpr int Ln    = 8192;     // doc length
static constexpr int Nn    = 128;      // output_sentence_num
static constexpr int Sn    = 256;      // output_sentence_len
static constexpr int DELIM = 5;
static constexpr int TPB   = 256;      // threads per block
static constexpr int TOKS  = Ln / TPB; // 32 tokens/thread == one 32-bit mask
static constexpr int NW    = TPB / 32; // 8 warps
static constexpr int SPLIT = 2;        // CTAs per row
static constexpr int KSEG  = Nn / SPLIT; // 64 segments per CTA

// exact int->float for 0 <= v < 2^23 without I2F (IADD + FADD)
__device__ __forceinline__ float i2f_small(int v)
{
    return __int_as_float(0x4B000000 + v) - 8388608.0f;
}

__global__ void zero_len(float* __restrict__ len_f)
{
    if (threadIdx.x < Bn) len_f[threadIdx.x] = 0.0f;
}

// d_out (float32): [ otp(B*N*S) | len_doc(B) | mask(B*N*S) ]
__global__ __launch_bounds__(TPB, 8)
void split_kernel(const int* __restrict__ x, float* __restrict__ out)
{
    __shared__ int s_dpos[Nn - 1];   // positions of first 127 delimiters
    __shared__ int s_woff[NW];       // per-warp scan offsets
    __shared__ int s_D;              // total delimiter count
    __shared__ int s_doc;            // nonempty sentences (this CTA's half)

    const int sp   = blockIdx.x;     // which half of the segments
    const int b    = blockIdx.y;     // row
    const int t    = threadIdx.x;
    const int lane = t & 31;
    const int warp = t >> 5;

    if (t == 0) s_doc = 0;

    const int* __restrict__ xrow = x + (size_t)b * Ln;

    // ---- Pass 1: load 32 tokens (8 x int4), build 32-bit delimiter mask ----
    const int base = t * TOKS;
    const int4* __restrict__ x4 = reinterpret_cast<const int4*>(xrow + base);

    unsigned dmask = 0;
    #pragma unroll
    for (int i = 0; i < TOKS / 4; i++) {
        int4 v = x4[i];
        dmask |= (unsigned)(v.x == DELIM) << (4 * i + 0);
        dmask |= (unsigned)(v.y == DELIM) << (4 * i + 1);
        dmask |= (unsigned)(v.z == DELIM) << (4 * i + 2);
        dmask |= (unsigned)(v.w == DELIM) << (4 * i + 3);
    }
    const int cnt = __popc(dmask);

    // warp inclusive scan of counts
    int incl = cnt;
    #pragma unroll
    for (int o = 1; o < 32; o <<= 1) {
        int n = __shfl_up_sync(0xffffffffu, incl, o);
        if (lane >= o) incl += n;
    }
    if (lane == 31) s_woff[warp] = incl;
    __syncthreads();

    if (warp == 0 && lane < NW) {
        int my  = s_woff[lane];
        int inc = my;
        #pragma unroll
        for (int o = 1; o < NW; o <<= 1) {
            int n = __shfl_up_sync((1u << NW) - 1u, inc, o);
            if (lane >= o) inc += n;
        }
        s_woff[lane] = inc - my;      // exclusive warp offset
        if (lane == NW - 1) s_D = inc;
    }
    __syncthreads();

    const int excl = incl - cnt + s_woff[warp];

    // ---- Pass 2: record first 127 delimiter positions from the bitmask ----
    if (dmask && excl < Nn - 1) {
        int r = excl;
        unsigned m = dmask;
        while (m && r < Nn - 1) {
            int bit = __ffs(m) - 1;
            s_dpos[r++] = base + bit;
            m &= m - 1;
        }
    }
    __syncthreads();

    const int D = s_D;

    float* __restrict__ otp_f  = out;
    float* __restrict__ len_f  = out + (size_t)Bn * Nn * Sn;
    float* __restrict__ mask_f = len_f + Bn;

    // ---- Emit: this CTA covers segments [sp*KSEG, (sp+1)*KSEG), one/warp ----
    int doc_local = 0;
    #pragma unroll 1
    for (int kk = warp; kk < KSEG; kk += NW) {
        const int k = sp * KSEG + kk;
        int start = 0, size = 0;
        if (k <= D) {
            start = (k == 0) ? 0 : (s_dpos[k - 1] + 1);
            if (k == Nn - 1 || k == D) size = (Ln + 1) - start;  // tail-merged / last
            else                        size = s_dpos[k] + 1 - start;
        }
        if (size <= 1) size = 0;   // lone-delimiter / unused -> all PAD

        const size_t row_off = ((size_t)b * Nn + k) * Sn;
        float*  __restrict__ otp_p = otp_f + row_off;
        float4* __restrict__ mask4 = reinterpret_cast<float4*>(mask_f + row_off);

        // 8 coalesced predicated loads, all issued up front (8-deep MLP)
        int v[8];
        #pragma unroll
        for (int i = 0; i < 8; i++) {
            const int s = i * 32 + lane;          // stride-1 across warp
            const int j = start + s;
            int val = 0;
            if (s < size) val = (j < Ln) ? xrow[j] : DELIM;
            v[i] = val;
        }

        int nz = (v[0] != 0) + (v[1] != 0) + (v[2] != 0) + (v[3] != 0)
               + (v[4] != 0) + (v[5] != 0) + (v[6] != 0) + (v[7] != 0);
        nz = __reduce_add_sync(0xffffffffu, nz);
        if (lane == 0 && nz > 0) doc_local++;

        // otp: 8 coalesced STG.32
        #pragma unroll
        for (int i = 0; i < 8; i++)
            otp_p[i * 32 + lane] = i2f_small(v[i]);

        // mask: no load dependency -> vector stores
        #pragma unroll
        for (int i = 0; i < 2; i++) {
            const int s0 = i * 128 + lane * 4;
            mask4[i * 32 + lane] = make_float4(
                (s0     < nz) ? 1.0f : 0.0f,
                (s0 + 1 < nz) ? 1.0f : 0.0f,
                (s0 + 2 < nz) ? 1.0f : 0.0f,
                (s0 + 3 < nz) ? 1.0f : 0.0f);
        }
    }

    if (lane == 0 && doc_local > 0) atomicAdd(&s_doc, doc_local);
    __syncthreads();
    if (t == 0 && s_doc > 0) atomicAdd(&len_f[b], (float)s_doc);
}

extern "C" void kernel_launch(void* const* d_in, const int* in_sizes, int n_in,
                              void* d_out, int out_size)
{
    const int* x  = (const int*)d_in[0];
    float* out    = (float*)d_out;
    float* len_f  = out + (size_t)Bn * Nn * Sn;

    zero_len<<<1, 512>>>(len_f);
    split_kernel<<<dim3(SPLIT, Bn), TPB>>>(x, out);
}

// round 12
// speedup vs baseline: 1.0386x; 1.0386x over previous
#include <cuda_runtime.h>
#include <cstdint>

// Fixed shapes per reference
static constexpr int Bn    = 512;      // batch
static constexpr int Ln    = 8192;     // doc length
static constexpr int Nn    = 128;      // output_sentence_num
static constexpr int Sn    = 256;      // output_sentence_len
static constexpr int DELIM = 5;

// Scan geometry
static constexpr int SC_TPB  = 512;
static constexpr int SC_TOKS = Ln / SC_TPB;  // 16 tokens/thread
static constexpr int SC_NW   = SC_TPB / 32;  // 16 warps

// Emit geometry (persistent, one wave)
static constexpr int EM_TPB   = 256;         // 8 warps
static constexpr int EM_NW    = EM_TPB / 32;
static constexpr int EM_GRID  = 148 * 8;     // 1184 CTAs (one full wave)
static constexpr int TASKS    = Bn * Nn;     // 65536 warp-tasks
static constexpr int CHUNK    = (TASKS + EM_GRID - 1) / EM_GRID;  // 56

// Per-(row,segment) descriptor {start, size} (size 0 => emit all PAD)
__device__ int2 g_seg[TASKS];

// exact int->float for 0 <= v < 2^23 without I2F (IADD + FADD)
__device__ __forceinline__ float i2f_small(int v)
{
    return __int_as_float(0x4B000000 + v) - 8388608.0f;
}

// ---------------- Kernel A: scan rows, build segment table ----------------
__global__ __launch_bounds__(SC_TPB, 4)
void scan_kernel(const int* __restrict__ x, float* __restrict__ len_f)
{
    __shared__ int s_dpos[Nn - 1];
    __shared__ int s_woff[SC_NW];
    __shared__ int s_D;

    const int b    = blockIdx.x;
    const int t    = threadIdx.x;
    const int lane = t & 31;
    const int warp = t >> 5;

    const int* __restrict__ xrow = x + (size_t)b * Ln;

    // load 16 tokens (4 x int4), build 16-bit delimiter mask
    const int base = t * SC_TOKS;
    const int4* __restrict__ x4 = reinterpret_cast<const int4*>(xrow + base);

    unsigned dmask = 0;
    #pragma unroll
    for (int i = 0; i < SC_TOKS / 4; i++) {
        int4 v = x4[i];
        dmask |= (unsigned)(v.x == DELIM) << (4 * i + 0);
        dmask |= (unsigned)(v.y == DELIM) << (4 * i + 1);
        dmask |= (unsigned)(v.z == DELIM) << (4 * i + 2);
        dmask |= (unsigned)(v.w == DELIM) << (4 * i + 3);
    }
    const int cnt = __popc(dmask);

    // warp inclusive scan
    int incl = cnt;
    #pragma unroll
    for (int o = 1; o < 32; o <<= 1) {
        int n = __shfl_up_sync(0xffffffffu, incl, o);
        if (lane >= o) incl += n;
    }
    if (lane == 31) s_woff[warp] = incl;
    __syncthreads();

    if (warp == 0 && lane < SC_NW) {
        int my  = s_woff[lane];
        int inc = my;
        #pragma unroll
        for (int o = 1; o < SC_NW; o <<= 1) {
            int n = __shfl_up_sync(0x0000ffffu, inc, o);
            if (lane >= o) inc += n;
        }
        s_woff[lane] = inc - my;
        if (lane == SC_NW - 1) s_D = inc;
    }
    __syncthreads();

    const int excl = incl - cnt + s_woff[warp];

    if (dmask && excl < Nn - 1) {
        int r = excl;
        unsigned m = dmask;
        while (m && r < Nn - 1) {
            int bit = __ffs(m) - 1;
            s_dpos[r++] = base + bit;
            m &= m - 1;
        }
    }
    __syncthreads();

    const int D = s_D;

    // threads 0..127 write sanitized descriptors
    if (t < Nn) {
        const int k = t;
        int start = 0, size = 0;
        if (k <= D) {
            start = (k == 0) ? 0 : (s_dpos[k - 1] + 1);
            if (k == Nn - 1 || k == D) size = (Ln + 1) - start;  // tail-merged / last
            else                        size = s_dpos[k] + 1 - start;
        }
        if (size <= 1) size = 0;   // lone delimiter / unused -> pure PAD
        g_seg[b * Nn + k] = make_int2(start, size);
    }
    if (t == 0) len_f[b] = 0.0f;
}

// ---------------- Kernel B: persistent emit, one warp per task ----------------
__global__ __launch_bounds__(EM_TPB, 8)
void emit_kernel(const int* __restrict__ x, float* __restrict__ out)
{
    const int t    = threadIdx.x;
    const int lane = t & 31;
    const int warp = t >> 5;

    float* __restrict__ otp_f  = out;
    float* __restrict__ len_f  = out + (size_t)Bn * Nn * Sn;
    float* __restrict__ mask_f = len_f + Bn;

    const int task_lo = blockIdx.x * CHUNK;
    const int task_hi = min(task_lo + CHUNK, TASKS);

    #pragma unroll 1
    for (int task = task_lo + warp; task < task_hi; task += EM_NW) {
        const int b = task >> 7;          // task / Nn
        const int k = task & (Nn - 1);    // task % Nn

        const int2 seg  = __ldg(&g_seg[task]);
        const int start = seg.x;
        const int size  = seg.y;          // 0 => pure PAD

        const int* __restrict__ xrow = x + (size_t)b * Ln;

        const size_t row_off = ((size_t)b * Nn + k) * Sn;
        float*  __restrict__ otp_p = otp_f + row_off;
        float4* __restrict__ mask4 = reinterpret_cast<float4*>(mask_f + row_off);

        // 8 coalesced predicated loads, issued up front (8-deep MLP)
        int v[8];
        #pragma unroll
        for (int i = 0; i < 8; i++) {
            const int s = i * 32 + lane;           // stride-1 across warp
            const int j = start + s;
            int val = 0;
            if (s < size) val = (j < Ln) ? xrow[j] : DELIM;
            v[i] = val;
        }

        int nz = (v[0] != 0) + (v[1] != 0) + (v[2] != 0) + (v[3] != 0)
               + (v[4] != 0) + (v[5] != 0) + (v[6] != 0) + (v[7] != 0);
        nz = __reduce_add_sync(0xffffffffu, nz);
        if (lane == 0 && nz > 0) atomicAdd(&len_f[b], 1.0f);

        // otp: 8 coalesced STG.32
        #pragma unroll
        for (int i = 0; i < 8; i++)
            otp_p[i * 32 + lane] = i2f_small(v[i]);

        // mask: vector stores
        #pragma unroll
        for (int i = 0; i < 2; i++) {
            const int s0 = i * 128 + lane * 4;
            mask4[i * 32 + lane] = make_float4(
                (s0     < nz) ? 1.0f : 0.0f,
                (s0 + 1 < nz) ? 1.0f : 0.0f,
                (s0 + 2 < nz) ? 1.0f : 0.0f,
                (s0 + 3 < nz) ? 1.0f : 0.0f);
        }
    }
}

extern "C" void kernel_launch(void* const* d_in, const int* in_sizes, int n_in,
                              void* d_out, int out_size)
{
    const int* x  = (const int*)d_in[0];
    float* out    = (float*)d_out;
    float* len_f  = out + (size_t)Bn * Nn * Sn;

    scan_kernel<<<Bn, SC_TPB>>>(x, len_f);
    emit_kernel<<<EM_GRID, EM_TPB>>>(x, out);
}

// round 13
// speedup vs baseline: 1.2033x; 1.1585x over previous
#include <cuda_runtime.h>
#include <cstdint>

// Fixed shapes per reference
static constexpr int Bn    = 512;      // batch
static constexpr int Ln    = 8192;     // doc length
static constexpr int Nn    = 128;      // output_sentence_num
static constexpr int Sn    = 256;      // output_sentence_len
static constexpr int DELIM = 5;
static constexpr int TPB   = 512;      // threads per block
static constexpr int TOKS  = Ln / TPB; // 16 tokens/thread
static constexpr int NW    = TPB / 32; // 16 warps

// Uniform-wave geometry: 148 SMs x 4 CTAs = 592 CTAs.
// Rows [0, FULL_ROWS) -> 1 CTA each; rows [FULL_ROWS, Bn) -> 2 CTAs each.
static constexpr int GRID      = 592;
static constexpr int FULL_ROWS = 2 * Bn - GRID;   // 432
static constexpr int SPLIT_LO  = FULL_ROWS;       // first split row

// exact int->float for 0 <= v < 2^23 without I2F (IADD + FADD)
__device__ __forceinline__ float i2f_small(int v)
{
    return __int_as_float(0x4B000000 + v) - 8388608.0f;
}

__global__ void zero_len_tail(float* __restrict__ len_f)
{
    const int i = SPLIT_LO + threadIdx.x;
    if (i < Bn) len_f[i] = 0.0f;
}

// d_out (float32): [ otp(B*N*S) | len_doc(B) | mask(B*N*S) ]
__global__ __launch_bounds__(TPB, 4)
void split_kernel(const int* __restrict__ x, float* __restrict__ out)
{
    __shared__ int s_dpos[Nn - 1];   // positions of first 127 delimiters
    __shared__ int s_woff[NW];       // per-warp scan offsets
    __shared__ int s_D;              // total delimiter count
    __shared__ int s_doc;            // # nonempty sentences (this CTA's share)

    // ---- CTA -> (row, segment range) mapping: uniform 592-CTA wave ----
    int b, k_lo, k_hi;
    const int bid = blockIdx.x;
    if (bid < FULL_ROWS) {
        b = bid; k_lo = 0; k_hi = Nn;
    } else {
        const int idx  = bid - FULL_ROWS;
        b    = SPLIT_LO + (idx >> 1);
        const int half = idx & 1;
        k_lo = half * (Nn / 2);
        k_hi = k_lo + (Nn / 2);
    }
    const bool split_row = (bid >= FULL_ROWS);

    const int t    = threadIdx.x;
    const int lane = t & 31;
    const int warp = t >> 5;

    if (t == 0) s_doc = 0;

    const int* __restrict__ xrow = x + (size_t)b * Ln;

    // ---- Pass 1: load 16 tokens (4 x int4), build 16-bit delimiter mask ----
    const int base = t * TOKS;
    const int4* __restrict__ x4 = reinterpret_cast<const int4*>(xrow + base);

    unsigned dmask = 0;
    #pragma unroll
    for (int i = 0; i < TOKS / 4; i++) {
        int4 v = x4[i];
        dmask |= (unsigned)(v.x == DELIM) << (4 * i + 0);
        dmask |= (unsigned)(v.y == DELIM) << (4 * i + 1);
        dmask |= (unsigned)(v.z == DELIM) << (4 * i + 2);
        dmask |= (unsigned)(v.w == DELIM) << (4 * i + 3);
    }
    const int cnt = __popc(dmask);

    // warp inclusive scan of counts
    int incl = cnt;
    #pragma unroll
    for (int o = 1; o < 32; o <<= 1) {
        int n = __shfl_up_sync(0xffffffffu, incl, o);
        if (lane >= o) incl += n;
    }
    if (lane == 31) s_woff[warp] = incl;
    __syncthreads();

    if (warp == 0 && lane < NW) {
        int my  = s_woff[lane];
        int inc = my;
        #pragma unroll
        for (int o = 1; o < NW; o <<= 1) {
            int n = __shfl_up_sync(0x0000ffffu, inc, o);
            if (lane >= o) inc += n;
        }
        s_woff[lane] = inc - my;      // exclusive warp offset
        if (lane == NW - 1) s_D = inc;
    }
    __syncthreads();

    const int excl = incl - cnt + s_woff[warp];

    // ---- Pass 2: record first 127 delimiter positions from the bitmask ----
    if (dmask && excl < Nn - 1) {
        int r = excl;
        unsigned m = dmask;
        while (m && r < Nn - 1) {
            int bit = __ffs(m) - 1;
            s_dpos[r++] = base + bit;
            m &= m - 1;
        }
    }
    __syncthreads();

    const int D = s_D;

    float* __restrict__ otp_f  = out;
    float* __restrict__ len_f  = out + (size_t)Bn * Nn * Sn;
    float* __restrict__ mask_f = len_f + Bn;

    // ---- Emit: one warp per segment in [k_lo, k_hi) ----
    int doc_local = 0;
    #pragma unroll 1
    for (int k = k_lo + warp; k < k_hi; k += NW) {
        int start = 0, size = 0;
        if (k <= D) {
            start = (k == 0) ? 0 : (s_dpos[k - 1] + 1);
            if (k == Nn - 1 || k == D) size = (Ln + 1) - start;  // tail-merged / last
            else                        size = s_dpos[k] + 1 - start;
        }
        if (size <= 1) size = 0;   // lone-delimiter / unused -> all PAD

        const size_t row_off = ((size_t)b * Nn + k) * Sn;
        float*  __restrict__ otp_p = otp_f + row_off;
        float4* __restrict__ mask4 = reinterpret_cast<float4*>(mask_f + row_off);

        // 8 coalesced predicated loads, all issued up front (8-deep MLP)
        int v[8];
        #pragma unroll
        for (int i = 0; i < 8; i++) {
            const int s = i * 32 + lane;          // stride-1 across warp
            const int j = start + s;
            int val = 0;
            if (s < size) val = (j < Ln) ? xrow[j] : DELIM;
            v[i] = val;
        }

        int nz = (v[0] != 0) + (v[1] != 0) + (v[2] != 0) + (v[3] != 0)
               + (v[4] != 0) + (v[5] != 0) + (v[6] != 0) + (v[7] != 0);
        nz = __reduce_add_sync(0xffffffffu, nz);
        if (lane == 0 && nz > 0) doc_local++;

        // otp: 8 coalesced STG.32
        #pragma unroll
        for (int i = 0; i < 8; i++)
            otp_p[i * 32 + lane] = i2f_small(v[i]);

        // mask: no load dependency -> vector stores
        #pragma unroll
        for (int i = 0; i < 2; i++) {
            const int s0 = i * 128 + lane * 4;
            mask4[i * 32 + lane] = make_float4(
                (s0     < nz) ? 1.0f : 0.0f,
                (s0 + 1 < nz) ? 1.0f : 0.0f,
                (s0 + 2 < nz) ? 1.0f : 0.0f,
                (s0 + 3 < nz) ? 1.0f : 0.0f);
        }
    }

    if (lane == 0 && doc_local > 0) atomicAdd(&s_doc, doc_local);
    __syncthreads();
    if (t == 0) {
        if (!split_row)          len_f[b] = (float)s_doc;           // sole owner
        else if (s_doc > 0)      atomicAdd(&len_f[b], (float)s_doc); // half owner
    }
}

extern "C" void kernel_launch(void* const* d_in, const int* in_sizes, int n_in,
                              void* d_out, int out_size)
{
    const int* x  = (const int*)d_in[0];
    float* out    = (float*)d_out;
    float* len_f  = out + (size_t)Bn * Nn * Sn;

    zero_len_tail<<<1, Bn - SPLIT_LO>>>(len_f);   // zero the 80 split-row entries
    split_kernel<<<GRID, TPB>>>(x, out);
}

// round 15
// speedup vs baseline: 1.2231x; 1.0165x over previous
#include <cuda_runtime.h>
#include <cstdint>

// Fixed shapes per reference
static constexpr int Bn    = 512;      // batch
static constexpr int Ln    = 8192;     // doc length
static constexpr int Nn    = 128;      // output_sentence_num
static constexpr int Sn    = 256;      // output_sentence_len
static constexpr int DELIM = 5;
static constexpr int TPB   = 512;      // threads per block
static constexpr int TOKS  = Ln / TPB; // 16 tokens/thread
static constexpr int NW    = TPB / 32; // 16 warps

// Uniform-wave geometry: 148 SMs x 4 CTAs = 592 CTAs.
// Rows [0, FULL_ROWS) -> 1 CTA each; rows [FULL_ROWS, Bn) -> 2 CTAs each.
static constexpr int GRID      = 592;
static constexpr int FULL_ROWS = 2 * Bn - GRID;   // 432
static constexpr int SPLIT_LO  = FULL_ROWS;       // first split row
static constexpr int NSPLIT    = Bn - SPLIT_LO;   // 80 split rows

// Self-cleaning rendezvous scratch for split-row len_doc.
// Zero-initialized at module load; the second-arriving CTA resets both words
// after consuming, so every graph replay starts from zero (deterministic).
__device__ int g_pcount[NSPLIT];
__device__ int g_cnt[NSPLIT];

// exact int->float for 0 <= v < 2^23 without I2F (IADD + FADD)
__device__ __forceinline__ float i2f_small(int v)
{
    return __int_as_float(0x4B000000 + v) - 8388608.0f;
}

// d_out (float32): [ otp(B*N*S) | len_doc(B) | mask(B*N*S) ]
__global__ __launch_bounds__(TPB, 4)
void split_kernel(const int* __restrict__ x, float* __restrict__ out)
{
    __shared__ int s_dpos[Nn - 1];   // positions of first 127 delimiters
    __shared__ int s_woff[NW];       // per-warp scan offsets
    __shared__ int s_D;              // total delimiter count
    __shared__ int s_doc;            // # nonempty sentences (this CTA's share)

    // ---- CTA -> (row, segment range) mapping: uniform 592-CTA wave ----
    int b, k_lo, k_hi;
    const int bid = blockIdx.x;
    if (bid < FULL_ROWS) {
        b = bid; k_lo = 0; k_hi = Nn;
    } else {
        const int idx  = bid - FULL_ROWS;
        b    = SPLIT_LO + (idx >> 1);
        const int half = idx & 1;
        k_lo = half * (Nn / 2);
        k_hi = k_lo + (Nn / 2);
    }
    const bool split_row = (bid >= FULL_ROWS);

    const int t    = threadIdx.x;
    const int lane = t & 31;
    const int warp = t >> 5;

    if (t == 0) s_doc = 0;

    const int* __restrict__ xrow = x + (size_t)b * Ln;

    // ---- Pass 1: load 16 tokens (4 x int4), build 16-bit delimiter mask ----
    const int base = t * TOKS;
    const int4* __restrict__ x4 = reinterpret_cast<const int4*>(xrow + base);

    unsigned dmask = 0;
    #pragma unroll
    for (int i = 0; i < TOKS / 4; i++) {
        int4 v = x4[i];
        dmask |= (unsigned)(v.x == DELIM) << (4 * i + 0);
        dmask |= (unsigned)(v.y == DELIM) << (4 * i + 1);
        dmask |= (unsigned)(v.z == DELIM) << (4 * i + 2);
        dmask |= (unsigned)(v.w == DELIM) << (4 * i + 3);
    }
    const int cnt = __popc(dmask);

    // warp inclusive scan of counts
    int incl = cnt;
    #pragma unroll
    for (int o = 1; o < 32; o <<= 1) {
        int n = __shfl_up_sync(0xffffffffu, incl, o);
        if (lane >= o) incl += n;
    }
    if (lane == 31) s_woff[warp] = incl;
    __syncthreads();

    if (warp == 0 && lane < NW) {
        int my  = s_woff[lane];
        int inc = my;
        #pragma unroll
        for (int o = 1; o < NW; o <<= 1) {
            int n = __shfl_up_sync(0x0000ffffu, inc, o);
            if (lane >= o) inc += n;
        }
        s_woff[lane] = inc - my;      // exclusive warp offset
        if (lane == NW - 1) s_D = inc;
    }
    __syncthreads();

    const int excl = incl - cnt + s_woff[warp];

    // ---- Pass 2: record first 127 delimiter positions from the bitmask ----
    if (dmask && excl < Nn - 1) {
        int r = excl;
        unsigned m = dmask;
        while (m && r < Nn - 1) {
            int bit = __ffs(m) - 1;
            s_dpos[r++] = base + bit;
            m &= m - 1;
        }
    }
    __syncthreads();

    const int D = s_D;

    float* __restrict__ otp_f  = out;
    float* __restrict__ len_f  = out + (size_t)Bn * Nn * Sn;
    float* __restrict__ mask_f = len_f + Bn;

    // ---- Emit: one warp per segment in [k_lo, k_hi) ----
    int doc_local = 0;
    #pragma unroll 1
    for (int k = k_lo + warp; k < k_hi; k += NW) {
        int start = 0, size = 0;
        if (k <= D) {
            start = (k == 0) ? 0 : (s_dpos[k - 1] + 1);
            if (k == Nn - 1 || k == D) size = (Ln + 1) - start;  // tail-merged / last
            else                        size = s_dpos[k] + 1 - start;
        }
        if (size <= 1) size = 0;   // lone-delimiter / unused -> all PAD

        const size_t row_off = ((size_t)b * Nn + k) * Sn;
        float*  __restrict__ otp_p = otp_f + row_off;
        float4* __restrict__ mask4 = reinterpret_cast<float4*>(mask_f + row_off);

        // 8 coalesced predicated loads, all issued up front (8-deep MLP)
        int v[8];
        #pragma unroll
        for (int i = 0; i < 8; i++) {
            const int s = i * 32 + lane;          // stride-1 across warp
            const int j = start + s;
            int val = 0;
            if (s < size) val = (j < Ln) ? xrow[j] : DELIM;
            v[i] = val;
        }

        int nz = (v[0] != 0) + (v[1] != 0) + (v[2] != 0) + (v[3] != 0)
               + (v[4] != 0) + (v[5] != 0) + (v[6] != 0) + (v[7] != 0);
        nz = __reduce_add_sync(0xffffffffu, nz);
        if (lane == 0 && nz > 0) doc_local++;

        // otp: 8 coalesced STG.32
        #pragma unroll
        for (int i = 0; i < 8; i++)
            otp_p[i * 32 + lane] = i2f_small(v[i]);

        // mask: no load dependency -> vector stores
        #pragma unroll
        for (int i = 0; i < 2; i++) {
            const int s0 = i * 128 + lane * 4;
            mask4[i * 32 + lane] = make_float4(
                (s0     < nz) ? 1.0f : 0.0f,
                (s0 + 1 < nz) ? 1.0f : 0.0f,
                (s0 + 2 < nz) ? 1.0f : 0.0f,
                (s0 + 3 < nz) ? 1.0f : 0.0f);
        }
    }

    if (lane == 0 && doc_local > 0) atomicAdd(&s_doc, doc_local);
    __syncthreads();

    if (t == 0) {
        if (!split_row) {
            len_f[b] = (float)s_doc;                 // sole owner: direct store
        } else {
            // two-CTA rendezvous; second arriver combines, writes, resets.
            const int idx = b - SPLIT_LO;
            atomicAdd(&g_pcount[idx], s_doc);
            __threadfence();
            const int old = atomicAdd(&g_cnt[idx], 1);
            if (old == 1) {                          // I'm second: both adds done
                __threadfence();
                const int total = *((volatile int*)&g_pcount[idx]);
                len_f[b] = (float)total;
                // reset scratch for the next (graph-replayed) launch
                g_pcount[idx] = 0;
                g_cnt[idx]    = 0;
            }
        }
    }
}

extern "C" void kernel_launch(void* const* d_in, const int* in_sizes, int n_in,
                              void* d_out, int out_size)
{
    const int* x = (const int*)d_in[0];
    split_kernel<<<GRID, TPB>>>(x, (float*)d_out);
}